// round 13
// baseline (speedup 1.0000x reference)
#include <cuda_runtime.h>
#include <math.h>
#include <stdint.h>

#define N_NODESC 50000
#define N_EDGESC 640000
#define N_GRAPHSC 64
#define HC 128
#define TL 80       // k_layer tile rows (micro 5)
#define T1 64       // k_layer1 tile rows (micro 4)
#define AST 132
typedef unsigned long long ull;

__device__ __align__(16) int   g_deg[N_NODESC];
__device__ __align__(16) int   g_off[N_NODESC + 1];
__device__ __align__(16) int   g_pos[N_NODESC];
__device__ __align__(16) int   g_srcs[N_EDGESC];
__device__ __align__(16) float g_h1[N_NODESC * HC];
__device__ __align__(16) float g_h2[N_NODESC * HC];
__device__ __align__(16) float g_pooled[N_GRAPHSC * 3 * HC];

__device__ __forceinline__ ull pack2(float x, float y) { ull r; asm("mov.b64 %0, {%1, %2};" : "=l"(r) : "f"(x), "f"(y)); return r; }
__device__ __forceinline__ void ffma2(ull& d, ull a, ull b) { asm("fma.rn.f32x2 %0, %1, %2, %3;" : "=l"(d) : "l"(a), "l"(b), "l"(d)); }
__device__ __forceinline__ float2 unpack2(ull p) { float2 f; asm("mov.b64 {%0, %1}, %2;" : "=f"(f.x), "=f"(f.y) : "l"(p)); return f; }
__device__ __forceinline__ void addf4(float4& a, float4 v) { a.x += v.x; a.y += v.y; a.z += v.z; a.w += v.w; }

// ---------------- CSR build ----------------
__global__ void k_init() {
    int i = blockIdx.x * blockDim.x + threadIdx.x;
    if (i < N_NODESC) g_deg[i] = 0;
    if (i < N_GRAPHSC * 3 * HC) g_pooled[i] = 0.f;
}
__global__ void k_hist(const int* __restrict__ ei) {
    int e4 = blockIdx.x * blockDim.x + threadIdx.x;
    if (e4 < N_EDGESC / 4) {
        int4 d = ((const int4*)(ei + N_EDGESC))[e4];
        atomicAdd(&g_deg[d.x], 1);
        atomicAdd(&g_deg[d.y], 1);
        atomicAdd(&g_deg[d.z], 1);
        atomicAdd(&g_deg[d.w], 1);
    }
}
__global__ void k_scan() {
    __shared__ int wsum[32];
    __shared__ int ctot;
    int tid = threadIdx.x, lane = tid & 31, wid = tid >> 5;
    int carry = 0;
    for (int base = 0; base < N_NODESC; base += 4096) {
        int i = base + tid * 4;
        int4 v = make_int4(0, 0, 0, 0);
        if (i < N_NODESC) v = ((const int4*)g_deg)[base / 4 + tid];
        int s0 = v.x, s1 = s0 + v.y, s2 = s1 + v.z, s3 = s2 + v.w;
        int incl = s3;
        #pragma unroll
        for (int o = 1; o < 32; o <<= 1) { int t = __shfl_up_sync(~0u, incl, o); if (lane >= o) incl += t; }
        if (lane == 31) wsum[wid] = incl;
        __syncthreads();
        if (wid == 0) {
            int s = wsum[lane], si = s;
            #pragma unroll
            for (int o = 1; o < 32; o <<= 1) { int t = __shfl_up_sync(~0u, si, o); if (lane >= o) si += t; }
            wsum[lane] = si - s;
            if (lane == 31) ctot = si;
        }
        __syncthreads();
        int excl = carry + wsum[wid] + incl - s3;
        if (i < N_NODESC) {
            g_off[i] = excl;          g_pos[i] = excl;
            g_off[i + 1] = excl + s0; g_pos[i + 1] = excl + s0;
            g_off[i + 2] = excl + s1; g_pos[i + 2] = excl + s1;
            g_off[i + 3] = excl + s2; g_pos[i + 3] = excl + s2;
        }
        carry += ctot;
        __syncthreads();
    }
    if (tid == 0) g_off[N_NODESC] = carry;
}
__global__ void k_fill(const int* __restrict__ ei) {
    int e4 = blockIdx.x * blockDim.x + threadIdx.x;
    if (e4 < N_EDGESC / 4) {
        int4 s = ((const int4*)ei)[e4];
        int4 d = ((const int4*)(ei + N_EDGESC))[e4];
        g_srcs[atomicAdd(&g_pos[d.x], 1)] = s.x;
        g_srcs[atomicAdd(&g_pos[d.y], 1)] = s.y;
        g_srcs[atomicAdd(&g_pos[d.z], 1)] = s.z;
        g_srcs[atomicAdd(&g_pos[d.w], 1)] = s.w;
    }
}

// ---------------- shared device pieces ----------------
template<int MR>
__device__ __forceinline__ void gemm_tileT(const float* __restrict__ At, int astride,
                                           const float* __restrict__ Bs, int K,
                                           ull acc[MR][4], int r0, int c0) {
    #pragma unroll 4
    for (int k = 0; k < K; k++) {
        float a[MR];
        #pragma unroll
        for (int i = 0; i < MR; i++) a[i] = At[(r0 + i) * astride + k];
        float4 bl = *(const float4*)&Bs[k * 128 + c0];
        float4 bh = *(const float4*)&Bs[k * 128 + c0 + 64];
        ull b0 = pack2(bl.x, bl.y), b1p = pack2(bl.z, bl.w);
        ull b2p = pack2(bh.x, bh.y), b3p = pack2(bh.z, bh.w);
        #pragma unroll
        for (int i = 0; i < MR; i++) {
            ull aa = pack2(a[i], a[i]);
            ffma2(acc[i][0], aa, b0); ffma2(acc[i][1], aa, b1p);
            ffma2(acc[i][2], aa, b2p); ffma2(acc[i][3], aa, b3p);
        }
    }
}
__device__ __forceinline__ void epi_relu(const ull acc[4], const float* __restrict__ bias,
                                         int c0, float4& lo, float4& hi) {
    float4 bl = *(const float4*)&bias[c0];
    float4 bh = *(const float4*)&bias[c0 + 64];
    float2 p0 = unpack2(acc[0]), p1 = unpack2(acc[1]);
    float2 p2 = unpack2(acc[2]), p3 = unpack2(acc[3]);
    lo = make_float4(fmaxf(p0.x + bl.x, 0.f), fmaxf(p0.y + bl.y, 0.f),
                     fmaxf(p1.x + bl.z, 0.f), fmaxf(p1.y + bl.w, 0.f));
    hi = make_float4(fmaxf(p2.x + bh.x, 0.f), fmaxf(p2.y + bh.y, 0.f),
                     fmaxf(p3.x + bh.z, 0.f), fmaxf(p3.y + bh.w, 0.f));
}
// pool tile (stride AST): 2 groups of HALF rows, 256 threads
__device__ __forceinline__ void pool_tile(const float* __restrict__ T,
                                          const int* __restrict__ batchS,
                                          int seg, int tid, int half) {
    int col = tid & 127, h0 = (tid >> 7) * half;
    float acc = 0.f; int cur = -1;
    for (int rr = h0; rr < h0 + half; rr++) {
        int g = batchS[rr];
        if (g < 0) break;
        if (g != cur) { if (cur >= 0) atomicAdd(&g_pooled[cur * 384 + seg * HC + col], acc); acc = 0.f; cur = g; }
        acc += T[rr * AST + col];
    }
    if (cur >= 0) atomicAdd(&g_pooled[cur * 384 + seg * HC + col], acc);
}

// ---------------- fused GIN layer (2,3): agg + MLP + pool, TILE 80, occ2 ----------------
__global__ __launch_bounds__(256, 2)
void k_layer(const float* __restrict__ hin,
             const float* __restrict__ W1, const float* __restrict__ b1v,
             const float* __restrict__ W2, const float* __restrict__ b2v,
             float* __restrict__ hout, const int* __restrict__ batch,
             int seg, int write_out) {
    extern __shared__ float sm[];
    float* As = sm;                 // TL x AST (agg -> mid -> h/pool)
    float* Bs = sm + TL * AST;      // 128 x 128 single weight buffer
    __shared__ int batchS[TL];

    int tid = threadIdx.x, lane = tid & 31, wid = tid >> 5;
    int row0 = blockIdx.x * TL;

    // stage W1 (overlaps agg loads)
    #pragma unroll
    for (int t = 0; t < 16; t++)
        ((float4*)Bs)[tid + t * 256] = ((const float4*)W1)[tid + t * 256];
    if (tid < TL) { int r = row0 + tid; batchS[tid] = (r < N_NODESC) ? batch[r] : -1; }

    // aggregation: 8 warps x 10 rows, MLP-8 with index prefetch
    const float4* xi = (const float4*)hin;
    for (int rr = wid; rr < TL; rr += 8) {
        int row = row0 + rr;
        float4 a0 = make_float4(0.f, 0.f, 0.f, 0.f);
        float4 a1 = a0, a2 = a0, a3 = a0, a4 = a0, a5 = a0, a6 = a0, a7 = a0;
        if (row < N_NODESC) {
            a0 = xi[row * 32 + lane];
            int s0 = g_off[row], s1 = g_off[row + 1], j = s0;
            if (j + 7 < s1) {
                int i0 = g_srcs[j],     i1 = g_srcs[j + 1], i2 = g_srcs[j + 2], i3 = g_srcs[j + 3];
                int i4 = g_srcs[j + 4], i5 = g_srcs[j + 5], i6 = g_srcs[j + 6], i7 = g_srcs[j + 7];
                for (; j + 15 < s1; j += 8) {
                    int n0 = g_srcs[j + 8],  n1 = g_srcs[j + 9],  n2 = g_srcs[j + 10], n3 = g_srcs[j + 11];
                    int n4 = g_srcs[j + 12], n5 = g_srcs[j + 13], n6 = g_srcs[j + 14], n7 = g_srcs[j + 15];
                    addf4(a0, xi[i0 * 32 + lane]); addf4(a1, xi[i1 * 32 + lane]);
                    addf4(a2, xi[i2 * 32 + lane]); addf4(a3, xi[i3 * 32 + lane]);
                    addf4(a4, xi[i4 * 32 + lane]); addf4(a5, xi[i5 * 32 + lane]);
                    addf4(a6, xi[i6 * 32 + lane]); addf4(a7, xi[i7 * 32 + lane]);
                    i0 = n0; i1 = n1; i2 = n2; i3 = n3; i4 = n4; i5 = n5; i6 = n6; i7 = n7;
                }
                addf4(a0, xi[i0 * 32 + lane]); addf4(a1, xi[i1 * 32 + lane]);
                addf4(a2, xi[i2 * 32 + lane]); addf4(a3, xi[i3 * 32 + lane]);
                addf4(a4, xi[i4 * 32 + lane]); addf4(a5, xi[i5 * 32 + lane]);
                addf4(a6, xi[i6 * 32 + lane]); addf4(a7, xi[i7 * 32 + lane]);
                j += 8;
            }
            for (; j + 1 < s1; j += 2) {
                addf4(a0, xi[g_srcs[j] * 32 + lane]);
                addf4(a1, xi[g_srcs[j + 1] * 32 + lane]);
            }
            if (j < s1) addf4(a0, xi[g_srcs[j] * 32 + lane]);
        }
        addf4(a0, a1); addf4(a2, a3); addf4(a4, a5); addf4(a6, a7);
        addf4(a0, a2); addf4(a4, a6); addf4(a0, a4);
        *(float4*)&As[rr * AST + lane * 4] = a0;
    }
    __syncthreads();

    int tx = tid & 15, ty = tid >> 4;
    int r0 = ty * 5, c0 = tx * 4;

    // GEMM1: mid = relu(agg @ W1 + b1)
    ull acc[5][4];
    #pragma unroll
    for (int i = 0; i < 5; i++) { acc[i][0] = acc[i][1] = acc[i][2] = acc[i][3] = 0ull; }
    gemm_tileT<5>(As, AST, Bs, 128, acc, r0, c0);
    __syncthreads();
    #pragma unroll
    for (int i = 0; i < 5; i++) {
        float4 lo, hi;
        epi_relu(acc[i], b1v, c0, lo, hi);
        *(float4*)&As[(r0 + i) * AST + c0] = lo;
        *(float4*)&As[(r0 + i) * AST + c0 + 64] = hi;
    }
    // restage W2
    #pragma unroll
    for (int t = 0; t < 16; t++)
        ((float4*)Bs)[tid + t * 256] = ((const float4*)W2)[tid + t * 256];
    __syncthreads();

    // GEMM2: h = relu(mid @ W2 + b2)
    #pragma unroll
    for (int i = 0; i < 5; i++) { acc[i][0] = acc[i][1] = acc[i][2] = acc[i][3] = 0ull; }
    gemm_tileT<5>(As, AST, Bs, 128, acc, r0, c0);
    __syncthreads();
    #pragma unroll
    for (int i = 0; i < 5; i++) {
        float4 lo, hi;
        epi_relu(acc[i], b2v, c0, lo, hi);
        int rr = r0 + i, row = row0 + rr;
        *(float4*)&As[rr * AST + c0] = lo;
        *(float4*)&As[rr * AST + c0 + 64] = hi;
        if (write_out && row < N_NODESC) {
            *(float4*)&hout[row * HC + c0] = lo;
            *(float4*)&hout[row * HC + c0 + 64] = hi;
        }
    }
    __syncthreads();
    pool_tile(As, batchS, seg, tid, TL / 2);
}

// ---------------- fused layer 1: agg8 + MLP(8->128->128) + pool, TILE 64 ----------------
__global__ __launch_bounds__(256, 2)
void k_layer1(const float* __restrict__ x,
              const float* __restrict__ W1, const float* __restrict__ b1v,
              const float* __restrict__ W2, const float* __restrict__ b2v,
              float* __restrict__ hout, const int* __restrict__ batch) {
    extern __shared__ float sm[];
    float* As = sm;                         // T1 x AST
    float* Bs = sm + T1 * AST;              // 128 x 128 (W2)
    float* A8 = Bs + 128 * 128;             // T1 x 8
    float* B8 = A8 + T1 * 8;                // 8 x 128 (W1)
    __shared__ int batchS[T1];

    int tid = threadIdx.x;
    int row0 = blockIdx.x * T1;

    ((float4*)B8)[tid] = ((const float4*)W1)[tid & 255];
    #pragma unroll
    for (int t = 0; t < 16; t++)
        ((float4*)Bs)[tid + t * 256] = ((const float4*)W2)[tid + t * 256];
    if (tid < T1) { int r = row0 + tid; batchS[tid] = (r < N_NODESC) ? batch[r] : -1; }

    // agg8: 2 threads per row (first 128 threads), MLP-4
    if (tid < 2 * T1) {
        int row_l = tid >> 1, half = tid & 1, row = row0 + row_l;
        float4 a0 = make_float4(0.f, 0.f, 0.f, 0.f);
        float4 a1 = a0, a2 = a0, a3 = a0;
        if (row < N_NODESC) {
            const float4* x4 = (const float4*)x;
            a0 = x4[row * 2 + half];
            int s0 = g_off[row], s1 = g_off[row + 1], j = s0;
            for (; j + 3 < s1; j += 4) {
                addf4(a0, x4[g_srcs[j] * 2 + half]);
                addf4(a1, x4[g_srcs[j + 1] * 2 + half]);
                addf4(a2, x4[g_srcs[j + 2] * 2 + half]);
                addf4(a3, x4[g_srcs[j + 3] * 2 + half]);
            }
            for (; j < s1; j++) addf4(a0, x4[g_srcs[j] * 2 + half]);
        }
        addf4(a0, a1); addf4(a2, a3); addf4(a0, a2);
        *(float4*)&A8[row_l * 8 + half * 4] = a0;
    }
    __syncthreads();

    int tx = tid & 15, ty = tid >> 4;
    int r0 = ty * 4, c0 = tx * 4;

    // GEMM1 (K=8): mid = relu(agg8 @ W1 + b1) -> As
    ull acc[4][4];
    #pragma unroll
    for (int i = 0; i < 4; i++) { acc[i][0] = acc[i][1] = acc[i][2] = acc[i][3] = 0ull; }
    gemm_tileT<4>(A8, 8, B8, 8, acc, r0, c0);
    #pragma unroll
    for (int i = 0; i < 4; i++) {
        float4 lo, hi;
        epi_relu(acc[i], b1v, c0, lo, hi);
        *(float4*)&As[(r0 + i) * AST + c0] = lo;
        *(float4*)&As[(r0 + i) * AST + c0 + 64] = hi;
    }
    __syncthreads();

    // GEMM2: h1 = relu(mid @ W2 + b2)
    #pragma unroll
    for (int i = 0; i < 4; i++) { acc[i][0] = acc[i][1] = acc[i][2] = acc[i][3] = 0ull; }
    gemm_tileT<4>(As, AST, Bs, 128, acc, r0, c0);
    __syncthreads();
    #pragma unroll
    for (int i = 0; i < 4; i++) {
        float4 lo, hi;
        epi_relu(acc[i], b2v, c0, lo, hi);
        int rr = r0 + i, row = row0 + rr;
        *(float4*)&As[rr * AST + c0] = lo;
        *(float4*)&As[rr * AST + c0 + 64] = hi;
        if (row < N_NODESC) {
            *(float4*)&hout[row * HC + c0] = lo;
            *(float4*)&hout[row * HC + c0 + 64] = hi;
        }
    }
    __syncthreads();
    pool_tile(As, batchS, 0, tid, T1 / 2);
}

// ---------------- classifier ----------------
__global__ void k_cls(const float* __restrict__ W1, const float* __restrict__ b1,
                      const float* __restrict__ bng, const float* __restrict__ bnb,
                      const float* __restrict__ bnm, const float* __restrict__ bnv,
                      const float* __restrict__ W2, const float* __restrict__ b2,
                      float* __restrict__ out) {
    __shared__ float ps[384];
    __shared__ float zs[256];
    int gph = blockIdx.x, tid = threadIdx.x;
    for (int i = tid; i < 384; i += 256) ps[i] = g_pooled[gph * 384 + i];
    __syncthreads();
    float acc = b1[tid];
    for (int k = 0; k < 384; k++) acc += ps[k] * W1[k * 256 + tid];
    acc = (acc - bnm[tid]) * rsqrtf(bnv[tid] + 1e-5f) * bng[tid] + bnb[tid];
    zs[tid] = fmaxf(acc, 0.f);
    __syncthreads();
    if (tid < 4) {
        float s = b2[tid];
        for (int k = 0; k < 256; k++) s += zs[k] * W2[k * 4 + tid];
        out[gph * 4 + tid] = s;
    }
}

// ---------------- launch ----------------
extern "C" void kernel_launch(void* const* d_in, const int* in_sizes, int n_in,
                              void* d_out, int out_size) {
    const float* x   = (const float*)d_in[0];
    const int* ei    = (const int*)d_in[1];
    const int* batch = (const int*)d_in[2];
    const float* l1W1 = (const float*)d_in[3];
    const float* l1b1 = (const float*)d_in[4];
    const float* l1W2 = (const float*)d_in[5];
    const float* l1b2 = (const float*)d_in[6];
    const float* l2W1 = (const float*)d_in[7];
    const float* l2b1 = (const float*)d_in[8];
    const float* l2W2 = (const float*)d_in[9];
    const float* l2b2 = (const float*)d_in[10];
    const float* l3W1 = (const float*)d_in[11];
    const float* l3b1 = (const float*)d_in[12];
    const float* l3W2 = (const float*)d_in[13];
    const float* l3b2 = (const float*)d_in[14];
    const float* cW1  = (const float*)d_in[15];
    const float* cb1  = (const float*)d_in[16];
    const float* bng  = (const float*)d_in[17];
    const float* bnb  = (const float*)d_in[18];
    const float* bnm  = (const float*)d_in[19];
    const float* bnv  = (const float*)d_in[20];
    const float* cW2  = (const float*)d_in[21];
    const float* cb2  = (const float*)d_in[22];
    float* out = (float*)d_out;

    float *h1, *h2;
    cudaGetSymbolAddress((void**)&h1, g_h1);
    cudaGetSymbolAddress((void**)&h2, g_h2);

    const int LAYER_SMEM  = (TL * AST + 128 * 128) * 4;                         // 107776
    const int LAYER1_SMEM = (T1 * AST + 128 * 128 + T1 * 8 + 8 * 128) * 4;      // 105472
    cudaFuncSetAttribute(k_layer,  cudaFuncAttributeMaxDynamicSharedMemorySize, LAYER_SMEM);
    cudaFuncSetAttribute(k_layer1, cudaFuncAttributeMaxDynamicSharedMemorySize, LAYER1_SMEM);

    const int blocksL  = (N_NODESC + TL - 1) / TL;   // 625
    const int blocks1  = (N_NODESC + T1 - 1) / T1;   // 782

    k_init<<<(N_NODESC + 255) / 256, 256>>>();
    k_hist<<<(N_EDGESC / 4 + 255) / 256, 256>>>(ei);
    k_scan<<<1, 1024>>>();
    k_fill<<<(N_EDGESC / 4 + 255) / 256, 256>>>(ei);

    k_layer1<<<blocks1, 256, LAYER1_SMEM>>>(x, l1W1, l1b1, l1W2, l1b2, h1, batch);
    k_layer<<<blocksL, 256, LAYER_SMEM>>>(h1, l2W1, l2b1, l2W2, l2b2, h2, batch, 1, 1);
    k_layer<<<blocksL, 256, LAYER_SMEM>>>(h2, l3W1, l3b1, l3W2, l3b2, h2, batch, 2, 0);

    k_cls<<<N_GRAPHSC, 256>>>(cW1, cb1, bng, bnb, bnm, bnv, cW2, cb2, out);
}

// round 16
// speedup vs baseline: 1.0187x; 1.0187x over previous
#include <cuda_runtime.h>
#include <math.h>
#include <stdint.h>

#define N_NODESC 50000
#define N_EDGESC 640000
#define N_GRAPHSC 64
#define HC 128
#define TILE 64
#define AST 132
typedef unsigned long long ull;

__device__ __align__(16) int   g_deg[N_NODESC];
__device__ __align__(16) int   g_off[N_NODESC + 1];
__device__ __align__(16) int   g_pos[N_NODESC];
__device__ __align__(16) int   g_srcs[N_EDGESC];
__device__ __align__(16) float g_h1[N_NODESC * HC];
__device__ __align__(16) float g_h2[N_NODESC * HC];
__device__ __align__(16) float g_pooled[N_GRAPHSC * 3 * HC];

__device__ __forceinline__ ull pack2(float x, float y) { ull r; asm("mov.b64 %0, {%1, %2};" : "=l"(r) : "f"(x), "f"(y)); return r; }
__device__ __forceinline__ void ffma2(ull& d, ull a, ull b) { asm("fma.rn.f32x2 %0, %1, %2, %3;" : "=l"(d) : "l"(a), "l"(b), "l"(d)); }
__device__ __forceinline__ float2 unpack2(ull p) { float2 f; asm("mov.b64 {%0, %1}, %2;" : "=f"(f.x), "=f"(f.y) : "l"(p)); return f; }
__device__ __forceinline__ void addf4(float4& a, float4 v) { a.x += v.x; a.y += v.y; a.z += v.z; a.w += v.w; }

// ---------------- CSR build ----------------
__global__ void k_init() {
    int i = blockIdx.x * blockDim.x + threadIdx.x;
    if (i < N_NODESC) g_deg[i] = 0;
    if (i < N_GRAPHSC * 3 * HC) g_pooled[i] = 0.f;
}
__global__ void k_hist(const int* __restrict__ ei) {
    int e4 = blockIdx.x * blockDim.x + threadIdx.x;
    if (e4 < N_EDGESC / 4) {
        int4 d = ((const int4*)(ei + N_EDGESC))[e4];
        atomicAdd(&g_deg[d.x], 1);
        atomicAdd(&g_deg[d.y], 1);
        atomicAdd(&g_deg[d.z], 1);
        atomicAdd(&g_deg[d.w], 1);
    }
}
__global__ void k_scan() {
    __shared__ int wsum[32];
    __shared__ int ctot;
    int tid = threadIdx.x, lane = tid & 31, wid = tid >> 5;
    int carry = 0;
    for (int base = 0; base < N_NODESC; base += 4096) {
        int i = base + tid * 4;
        int4 v = make_int4(0, 0, 0, 0);
        if (i < N_NODESC) v = ((const int4*)g_deg)[base / 4 + tid];
        int s0 = v.x, s1 = s0 + v.y, s2 = s1 + v.z, s3 = s2 + v.w;
        int incl = s3;
        #pragma unroll
        for (int o = 1; o < 32; o <<= 1) { int t = __shfl_up_sync(~0u, incl, o); if (lane >= o) incl += t; }
        if (lane == 31) wsum[wid] = incl;
        __syncthreads();
        if (wid == 0) {
            int s = wsum[lane], si = s;
            #pragma unroll
            for (int o = 1; o < 32; o <<= 1) { int t = __shfl_up_sync(~0u, si, o); if (lane >= o) si += t; }
            wsum[lane] = si - s;
            if (lane == 31) ctot = si;
        }
        __syncthreads();
        int excl = carry + wsum[wid] + incl - s3;
        if (i < N_NODESC) {
            g_off[i] = excl;          g_pos[i] = excl;
            g_off[i + 1] = excl + s0; g_pos[i + 1] = excl + s0;
            g_off[i + 2] = excl + s1; g_pos[i + 2] = excl + s1;
            g_off[i + 3] = excl + s2; g_pos[i + 3] = excl + s2;
        }
        carry += ctot;
        __syncthreads();
    }
    if (tid == 0) g_off[N_NODESC] = carry;
}
__global__ void k_fill(const int* __restrict__ ei) {
    int e4 = blockIdx.x * blockDim.x + threadIdx.x;
    if (e4 < N_EDGESC / 4) {
        int4 s = ((const int4*)ei)[e4];
        int4 d = ((const int4*)(ei + N_EDGESC))[e4];
        g_srcs[atomicAdd(&g_pos[d.x], 1)] = s.x;
        g_srcs[atomicAdd(&g_pos[d.y], 1)] = s.y;
        g_srcs[atomicAdd(&g_pos[d.z], 1)] = s.z;
        g_srcs[atomicAdd(&g_pos[d.w], 1)] = s.w;
    }
}

// ---------------- GEMM micro-kernels ----------------
// micro 8 rows x 4 cols: 32 tx x 8 ty, B traffic halved vs 16x16 layout
__device__ __forceinline__ void gemm84(const float* __restrict__ At, int astride,
                                       const float* __restrict__ Bs, int K,
                                       ull acc[8][2], int r0, int c0) {
    #pragma unroll 4
    for (int k = 0; k < K; k++) {
        float a[8];
        #pragma unroll
        for (int i = 0; i < 8; i++) a[i] = At[(r0 + i) * astride + k];
        float4 b = *(const float4*)&Bs[k * 128 + c0];
        ull b0 = pack2(b.x, b.y), b1 = pack2(b.z, b.w);
        #pragma unroll
        for (int i = 0; i < 8; i++) {
            ull aa = pack2(a[i], a[i]);
            ffma2(acc[i][0], aa, b0);
            ffma2(acc[i][1], aa, b1);
        }
    }
}
__device__ __forceinline__ float4 epi84(const ull acc[2], float4 bl) {
    float2 p0 = unpack2(acc[0]), p1 = unpack2(acc[1]);
    return make_float4(fmaxf(p0.x + bl.x, 0.f), fmaxf(p0.y + bl.y, 0.f),
                       fmaxf(p1.x + bl.z, 0.f), fmaxf(p1.y + bl.w, 0.f));
}
// legacy 16x16 micro (4 rows x 8 split cols) for layer1
template<int MR>
__device__ __forceinline__ void gemm_tileT(const float* __restrict__ At, int astride,
                                           const float* __restrict__ Bs, int K,
                                           ull acc[MR][4], int r0, int c0) {
    #pragma unroll 4
    for (int k = 0; k < K; k++) {
        float a[MR];
        #pragma unroll
        for (int i = 0; i < MR; i++) a[i] = At[(r0 + i) * astride + k];
        float4 bl = *(const float4*)&Bs[k * 128 + c0];
        float4 bh = *(const float4*)&Bs[k * 128 + c0 + 64];
        ull b0 = pack2(bl.x, bl.y), b1p = pack2(bl.z, bl.w);
        ull b2p = pack2(bh.x, bh.y), b3p = pack2(bh.z, bh.w);
        #pragma unroll
        for (int i = 0; i < MR; i++) {
            ull aa = pack2(a[i], a[i]);
            ffma2(acc[i][0], aa, b0); ffma2(acc[i][1], aa, b1p);
            ffma2(acc[i][2], aa, b2p); ffma2(acc[i][3], aa, b3p);
        }
    }
}
__device__ __forceinline__ void epi_relu(const ull acc[4], const float* __restrict__ bias,
                                         int c0, float4& lo, float4& hi) {
    float4 bl = *(const float4*)&bias[c0];
    float4 bh = *(const float4*)&bias[c0 + 64];
    float2 p0 = unpack2(acc[0]), p1 = unpack2(acc[1]);
    float2 p2 = unpack2(acc[2]), p3 = unpack2(acc[3]);
    lo = make_float4(fmaxf(p0.x + bl.x, 0.f), fmaxf(p0.y + bl.y, 0.f),
                     fmaxf(p1.x + bl.z, 0.f), fmaxf(p1.y + bl.w, 0.f));
    hi = make_float4(fmaxf(p2.x + bh.x, 0.f), fmaxf(p2.y + bh.y, 0.f),
                     fmaxf(p3.x + bh.z, 0.f), fmaxf(p3.y + bh.w, 0.f));
}
__device__ __forceinline__ void pool_tile(const float* __restrict__ T,
                                          const int* __restrict__ batchS, int seg, int tid) {
    int col = tid & 127, h0 = (tid >> 7) * 32;
    float acc = 0.f; int cur = -1;
    for (int rr = h0; rr < h0 + 32; rr++) {
        int g = batchS[rr];
        if (g < 0) break;
        if (g != cur) { if (cur >= 0) atomicAdd(&g_pooled[cur * 384 + seg * HC + col], acc); acc = 0.f; cur = g; }
        acc += T[rr * AST + col];
    }
    if (cur >= 0) atomicAdd(&g_pooled[cur * 384 + seg * HC + col], acc);
}

// ---------------- fused GIN layer (2,3): agg + MLP + pool, occ2 ----------------
__global__ __launch_bounds__(256, 2)
void k_layer(const float* __restrict__ hin,
             const float* __restrict__ W1, const float* __restrict__ b1v,
             const float* __restrict__ W2, const float* __restrict__ b2v,
             float* __restrict__ hout, const int* __restrict__ batch,
             int seg, int write_out) {
    extern __shared__ float sm[];
    float* As = sm;                 // TILE x AST (agg -> mid -> h/pool)
    float* Bs = sm + TILE * AST;    // 128 x 128 single weight buffer
    __shared__ int batchS[TILE];

    int tid = threadIdx.x, lane = tid & 31, wid = tid >> 5;
    int row0 = blockIdx.x * TILE;

    // stage W1 (overlaps agg loads below)
    #pragma unroll
    for (int t = 0; t < 16; t++)
        ((float4*)Bs)[tid + t * 256] = ((const float4*)W1)[tid + t * 256];
    if (tid < TILE) { int r = row0 + tid; batchS[tid] = (r < N_NODESC) ? batch[r] : -1; }

    // aggregation: 8 warps x 8 rows, MLP-8 unroll
    const float4* xi = (const float4*)hin;
    for (int rr = wid; rr < TILE; rr += 8) {
        int row = row0 + rr;
        float4 a0 = make_float4(0.f, 0.f, 0.f, 0.f);
        float4 a1 = a0, a2 = a0, a3 = a0, a4 = a0, a5 = a0, a6 = a0, a7 = a0;
        if (row < N_NODESC) {
            a0 = xi[row * 32 + lane];
            int s0 = g_off[row], s1 = g_off[row + 1], j = s0;
            for (; j + 7 < s1; j += 8) {
                int i0 = g_srcs[j],     i1 = g_srcs[j + 1], i2 = g_srcs[j + 2], i3 = g_srcs[j + 3];
                int i4 = g_srcs[j + 4], i5 = g_srcs[j + 5], i6 = g_srcs[j + 6], i7 = g_srcs[j + 7];
                addf4(a0, xi[i0 * 32 + lane]); addf4(a1, xi[i1 * 32 + lane]);
                addf4(a2, xi[i2 * 32 + lane]); addf4(a3, xi[i3 * 32 + lane]);
                addf4(a4, xi[i4 * 32 + lane]); addf4(a5, xi[i5 * 32 + lane]);
                addf4(a6, xi[i6 * 32 + lane]); addf4(a7, xi[i7 * 32 + lane]);
            }
            for (; j + 1 < s1; j += 2) {
                addf4(a0, xi[g_srcs[j] * 32 + lane]);
                addf4(a1, xi[g_srcs[j + 1] * 32 + lane]);
            }
            if (j < s1) addf4(a0, xi[g_srcs[j] * 32 + lane]);
        }
        addf4(a0, a1); addf4(a2, a3); addf4(a4, a5); addf4(a6, a7);
        addf4(a0, a2); addf4(a4, a6); addf4(a0, a4);
        *(float4*)&As[rr * AST + lane * 4] = a0;
    }
    __syncthreads();

    int tx = tid & 31, ty = tid >> 5;   // 32 x 8
    int r0 = ty * 8, c0 = tx * 4;

    // GEMM1: mid = relu(agg @ W1 + b1)
    ull acc[8][2];
    #pragma unroll
    for (int i = 0; i < 8; i++) { acc[i][0] = acc[i][1] = 0ull; }
    gemm84(As, AST, Bs, 128, acc, r0, c0);
    __syncthreads();     // reads of As(agg) and Bs(W1) done
    {
        float4 bl = *(const float4*)&b1v[c0];
        #pragma unroll
        for (int i = 0; i < 8; i++)
            *(float4*)&As[(r0 + i) * AST + c0] = epi84(acc[i], bl);
    }
    // restage W2
    #pragma unroll
    for (int t = 0; t < 16; t++)
        ((float4*)Bs)[tid + t * 256] = ((const float4*)W2)[tid + t * 256];
    __syncthreads();

    // GEMM2: h = relu(mid @ W2 + b2)
    #pragma unroll
    for (int i = 0; i < 8; i++) { acc[i][0] = acc[i][1] = 0ull; }
    gemm84(As, AST, Bs, 128, acc, r0, c0);
    __syncthreads();     // reads of As(mid) done
    {
        float4 bl = *(const float4*)&b2v[c0];
        #pragma unroll
        for (int i = 0; i < 8; i++) {
            int rr = r0 + i, row = row0 + rr;
            float4 v = epi84(acc[i], bl);
            *(float4*)&As[rr * AST + c0] = v;
            if (write_out && row < N_NODESC)
                *(float4*)&hout[row * HC + c0] = v;
        }
    }
    __syncthreads();
    pool_tile(As, batchS, seg, tid);
}

// ---------------- fused layer 1: agg8 + MLP(8->128->128) + pool ----------------
__global__ __launch_bounds__(256, 2)
void k_layer1(const float* __restrict__ x,
              const float* __restrict__ W1, const float* __restrict__ b1v,
              const float* __restrict__ W2, const float* __restrict__ b2v,
              float* __restrict__ hout, const int* __restrict__ batch) {
    extern __shared__ float sm[];
    float* As = sm;                         // TILE x AST
    float* Bs = sm + TILE * AST;            // 128 x 128 (W2)
    float* A8 = Bs + 128 * 128;             // TILE x 8
    float* B8 = A8 + TILE * 8;              // 8 x 128 (W1)
    __shared__ int batchS[TILE];

    int tid = threadIdx.x;
    int row0 = blockIdx.x * TILE;

    ((float4*)B8)[tid] = ((const float4*)W1)[tid & 255];
    #pragma unroll
    for (int t = 0; t < 16; t++)
        ((float4*)Bs)[tid + t * 256] = ((const float4*)W2)[tid + t * 256];
    if (tid < TILE) { int r = row0 + tid; batchS[tid] = (r < N_NODESC) ? batch[r] : -1; }

    // agg8: 2 threads per row (first 128 threads), MLP-4
    if (tid < 2 * TILE) {
        int row_l = tid >> 1, half = tid & 1, row = row0 + row_l;
        float4 a0 = make_float4(0.f, 0.f, 0.f, 0.f);
        float4 a1 = a0, a2 = a0, a3 = a0;
        if (row < N_NODESC) {
            const float4* x4 = (const float4*)x;
            a0 = x4[row * 2 + half];
            int s0 = g_off[row], s1 = g_off[row + 1], j = s0;
            for (; j + 3 < s1; j += 4) {
                addf4(a0, x4[g_srcs[j] * 2 + half]);
                addf4(a1, x4[g_srcs[j + 1] * 2 + half]);
                addf4(a2, x4[g_srcs[j + 2] * 2 + half]);
                addf4(a3, x4[g_srcs[j + 3] * 2 + half]);
            }
            for (; j < s1; j++) addf4(a0, x4[g_srcs[j] * 2 + half]);
        }
        addf4(a0, a1); addf4(a2, a3); addf4(a0, a2);
        *(float4*)&A8[row_l * 8 + half * 4] = a0;
    }
    __syncthreads();

    int tx = tid & 15, ty = tid >> 4;
    int r0 = ty * 4, c0 = tx * 4;

    // GEMM1 (K=8): mid = relu(agg8 @ W1 + b1) -> As
    ull acc[4][4];
    #pragma unroll
    for (int i = 0; i < 4; i++) { acc[i][0] = acc[i][1] = acc[i][2] = acc[i][3] = 0ull; }
    gemm_tileT<4>(A8, 8, B8, 8, acc, r0, c0);
    #pragma unroll
    for (int i = 0; i < 4; i++) {
        float4 lo, hi;
        epi_relu(acc[i], b1v, c0, lo, hi);
        *(float4*)&As[(r0 + i) * AST + c0] = lo;
        *(float4*)&As[(r0 + i) * AST + c0 + 64] = hi;
    }
    __syncthreads();

    // GEMM2: h1 = relu(mid @ W2 + b2)
    #pragma unroll
    for (int i = 0; i < 4; i++) { acc[i][0] = acc[i][1] = acc[i][2] = acc[i][3] = 0ull; }
    gemm_tileT<4>(As, AST, Bs, 128, acc, r0, c0);
    __syncthreads();
    #pragma unroll
    for (int i = 0; i < 4; i++) {
        float4 lo, hi;
        epi_relu(acc[i], b2v, c0, lo, hi);
        int rr = r0 + i, row = row0 + rr;
        *(float4*)&As[rr * AST + c0] = lo;
        *(float4*)&As[rr * AST + c0 + 64] = hi;
        if (row < N_NODESC) {
            *(float4*)&hout[row * HC + c0] = lo;
            *(float4*)&hout[row * HC + c0 + 64] = hi;
        }
    }
    __syncthreads();
    pool_tile(As, batchS, 0, tid);
}

// ---------------- classifier ----------------
__global__ void k_cls(const float* __restrict__ W1, const float* __restrict__ b1,
                      const float* __restrict__ bng, const float* __restrict__ bnb,
                      const float* __restrict__ bnm, const float* __restrict__ bnv,
                      const float* __restrict__ W2, const float* __restrict__ b2,
                      float* __restrict__ out) {
    __shared__ float ps[384];
    __shared__ float zs[256];
    int gph = blockIdx.x, tid = threadIdx.x;
    for (int i = tid; i < 384; i += 256) ps[i] = g_pooled[gph * 384 + i];
    __syncthreads();
    float acc = b1[tid];
    for (int k = 0; k < 384; k++) acc += ps[k] * W1[k * 256 + tid];
    acc = (acc - bnm[tid]) * rsqrtf(bnv[tid] + 1e-5f) * bng[tid] + bnb[tid];
    zs[tid] = fmaxf(acc, 0.f);
    __syncthreads();
    if (tid < 4) {
        float s = b2[tid];
        for (int k = 0; k < 256; k++) s += zs[k] * W2[k * 4 + tid];
        out[gph * 4 + tid] = s;
    }
}

// ---------------- launch ----------------
extern "C" void kernel_launch(void* const* d_in, const int* in_sizes, int n_in,
                              void* d_out, int out_size) {
    const float* x   = (const float*)d_in[0];
    const int* ei    = (const int*)d_in[1];
    const int* batch = (const int*)d_in[2];
    const float* l1W1 = (const float*)d_in[3];
    const float* l1b1 = (const float*)d_in[4];
    const float* l1W2 = (const float*)d_in[5];
    const float* l1b2 = (const float*)d_in[6];
    const float* l2W1 = (const float*)d_in[7];
    const float* l2b1 = (const float*)d_in[8];
    const float* l2W2 = (const float*)d_in[9];
    const float* l2b2 = (const float*)d_in[10];
    const float* l3W1 = (const float*)d_in[11];
    const float* l3b1 = (const float*)d_in[12];
    const float* l3W2 = (const float*)d_in[13];
    const float* l3b2 = (const float*)d_in[14];
    const float* cW1  = (const float*)d_in[15];
    const float* cb1  = (const float*)d_in[16];
    const float* bng  = (const float*)d_in[17];
    const float* bnb  = (const float*)d_in[18];
    const float* bnm  = (const float*)d_in[19];
    const float* bnv  = (const float*)d_in[20];
    const float* cW2  = (const float*)d_in[21];
    const float* cb2  = (const float*)d_in[22];
    float* out = (float*)d_out;

    float *h1, *h2;
    cudaGetSymbolAddress((void**)&h1, g_h1);
    cudaGetSymbolAddress((void**)&h2, g_h2);

    const int LAYER_SMEM  = (TILE * AST + 128 * 128) * 4;                       // 99328
    const int LAYER1_SMEM = LAYER_SMEM + (TILE * 8 + 8 * 128) * 4;              // 105472
    cudaFuncSetAttribute(k_layer,  cudaFuncAttributeMaxDynamicSharedMemorySize, LAYER_SMEM);
    cudaFuncSetAttribute(k_layer1, cudaFuncAttributeMaxDynamicSharedMemorySize, LAYER1_SMEM);

    const int blocks = (N_NODESC + TILE - 1) / TILE;   // 782

    k_init<<<(N_NODESC + 255) / 256, 256>>>();
    k_hist<<<(N_EDGESC / 4 + 255) / 256, 256>>>(ei);
    k_scan<<<1, 1024>>>();
    k_fill<<<(N_EDGESC / 4 + 255) / 256, 256>>>(ei);

    k_layer1<<<blocks, 256, LAYER1_SMEM>>>(x, l1W1, l1b1, l1W2, l1b2, h1, batch);
    k_layer<<<blocks, 256, LAYER_SMEM>>>(h1, l2W1, l2b1, l2W2, l2b2, h2, batch, 1, 1);
    k_layer<<<blocks, 256, LAYER_SMEM>>>(h2, l3W1, l3b1, l3W2, l3b2, h2, batch, 2, 0);

    k_cls<<<N_GRAPHSC, 256>>>(cW1, cb1, bng, bnb, bnm, bnv, cW2, cb2, out);
}